// round 5
// baseline (speedup 1.0000x reference)
#include <cuda_runtime.h>

#define NBINS 28
#define HID   16
#define FEAT  8
#define EPT   4      // elements per thread
#define TPB   128

// mhless table: t[dl] = exp(ml_mlp(dl) - 0.25*dl) for dl = 1..40
__device__ float g_mhless[41];

__device__ __forceinline__ float sigmoidf(float v) {
    return 1.0f / (1.0f + __expf(-v));
}

// ---------------------------------------------------------------------------
// Init kernel: one tiny block computes the ml-MLP table for dl = 1..40 and
// writes dl2_scores (dl = 1..28) into the bin region of d_out. Runs every
// launch (d_out is poisoned before timing), and is deterministic.
// ---------------------------------------------------------------------------
__global__ void dnn_init_kernel(
    const float* __restrict__ ml_W1, const float* __restrict__ ml_b1,
    const float* __restrict__ ml_W2, const float* __restrict__ ml_b2,
    const float* __restrict__ ml_W3, const float* __restrict__ ml_b3,
    float* __restrict__ out_bins)
{
    int t = threadIdx.x;
    if (t >= 40) return;
    float dl = (float)(t + 1);

    float h1[HID];
    #pragma unroll
    for (int o = 0; o < HID; o++)
        h1[o] = sigmoidf(fmaf(dl, ml_W1[o], ml_b1[o]));

    float h2[HID];
    #pragma unroll
    for (int o = 0; o < HID; o++) {
        float a = ml_b2[o];
        #pragma unroll
        for (int i = 0; i < HID; i++)
            a = fmaf(h1[i], ml_W2[i * HID + o], a);
        h2[o] = sigmoidf(a);
    }

    float phi = ml_b3[0];
    #pragma unroll
    for (int i = 0; i < HID; i++)
        phi = fmaf(h2[i], ml_W3[i], phi);

    float v = __expf(phi - 0.25f * dl);
    g_mhless[t + 1] = v;           // table for the main kernel
    if (t < NBINS) out_bins[t] = v; // dl2_scores baseline; atomics add on top
}

// ---------------------------------------------------------------------------
// Main kernel: mh MLP for all N rows, fused epilogue (exp, table add,
// binned segment-sum via shared-memory privatization).
// ---------------------------------------------------------------------------
__global__ __launch_bounds__(TPB)
void dnn_main_kernel(
    const float* __restrict__ x_feat,
    const float* __restrict__ W1, const float* __restrict__ b1,
    const float* __restrict__ W2, const float* __restrict__ b2,
    const float* __restrict__ W3, const float* __restrict__ b3,
    const int*   __restrict__ del_lens,
    const int*   __restrict__ mh_len,
    float* __restrict__ out,
    float* __restrict__ out_bins,
    int n)
{
    __shared__ float sW1[FEAT * HID];
    __shared__ float sW2[HID * HID];
    __shared__ float sb1[HID], sb2[HID], sW3[HID];
    __shared__ float sb3;
    __shared__ float stab[41];
    __shared__ float sbins[NBINS];

    const int tid = threadIdx.x;

    if (tid < FEAT * HID) sW1[tid] = W1[tid];
    for (int i = tid; i < HID * HID; i += TPB) sW2[i] = W2[i];
    if (tid < HID) { sb1[tid] = b1[tid]; sb2[tid] = b2[tid]; sW3[tid] = W3[tid]; }
    if (tid == 0) sb3 = b3[0];
    if (tid < 41) stab[tid] = g_mhless[tid];
    if (tid < NBINS) sbins[tid] = 0.0f;
    __syncthreads();

    const int base = blockIdx.x * (TPB * EPT) + tid;

    int  idx[EPT];
    bool valid[EPT];
    float x[EPT][FEAT];

    #pragma unroll
    for (int e = 0; e < EPT; e++) {
        idx[e]   = base + e * TPB;
        valid[e] = (idx[e] < n);
        int j = valid[e] ? idx[e] : 0;
        float4 a = *reinterpret_cast<const float4*>(x_feat + (size_t)j * FEAT);
        float4 c = *reinterpret_cast<const float4*>(x_feat + (size_t)j * FEAT + 4);
        x[e][0] = a.x; x[e][1] = a.y; x[e][2] = a.z; x[e][3] = a.w;
        x[e][4] = c.x; x[e][5] = c.y; x[e][6] = c.z; x[e][7] = c.w;
    }

    // ---- Layer 1: [EPT,8] @ [8,16] + b1, sigmoid ----
    float h1[EPT][HID];
    #pragma unroll
    for (int e = 0; e < EPT; e++)
        #pragma unroll
        for (int o = 0; o < HID; o++) h1[e][o] = sb1[o];

    #pragma unroll
    for (int i = 0; i < FEAT; i++) {
        float w[HID];
        #pragma unroll
        for (int o = 0; o < HID; o += 4) {
            float4 wv = *reinterpret_cast<const float4*>(&sW1[i * HID + o]);
            w[o] = wv.x; w[o+1] = wv.y; w[o+2] = wv.z; w[o+3] = wv.w;
        }
        #pragma unroll
        for (int e = 0; e < EPT; e++)
            #pragma unroll
            for (int o = 0; o < HID; o++)
                h1[e][o] = fmaf(x[e][i], w[o], h1[e][o]);
    }
    #pragma unroll
    for (int e = 0; e < EPT; e++)
        #pragma unroll
        for (int o = 0; o < HID; o++) h1[e][o] = sigmoidf(h1[e][o]);

    // ---- Layer 2: [EPT,16] @ [16,16] + b2, sigmoid ----
    float h2[EPT][HID];
    #pragma unroll
    for (int e = 0; e < EPT; e++)
        #pragma unroll
        for (int o = 0; o < HID; o++) h2[e][o] = sb2[o];

    #pragma unroll
    for (int i = 0; i < HID; i++) {
        float w[HID];
        #pragma unroll
        for (int o = 0; o < HID; o += 4) {
            float4 wv = *reinterpret_cast<const float4*>(&sW2[i * HID + o]);
            w[o] = wv.x; w[o+1] = wv.y; w[o+2] = wv.z; w[o+3] = wv.w;
        }
        #pragma unroll
        for (int e = 0; e < EPT; e++)
            #pragma unroll
            for (int o = 0; o < HID; o++)
                h2[e][o] = fmaf(h1[e][i], w[o], h2[e][o]);
    }

    // ---- Layer 3 + epilogue ----
    #pragma unroll
    for (int e = 0; e < EPT; e++) {
        float phi = sb3;
        #pragma unroll
        for (int i = 0; i < HID; i++)
            phi = fmaf(sigmoidf(h2[e][i]), sW3[i], phi);

        if (valid[e]) {
            int d  = del_lens[idx[e]];
            int mh = mh_len[idx[e]];
            float score = __expf(fmaf(-0.25f, (float)d, phi));
            float contrib = 0.0f;
            if (d == mh && d >= 1 && d <= 40) contrib = stab[d];
            out[idx[e]] = score + contrib;
            if (d <= NBINS) atomicAdd(&sbins[d - 1], score);
        }
    }

    __syncthreads();
    if (tid < NBINS) {
        float v = sbins[tid];
        if (v != 0.0f) atomicAdd(&out_bins[tid], v);
    }
}

// ---------------------------------------------------------------------------
// Launch
// ---------------------------------------------------------------------------
extern "C" void kernel_launch(void* const* d_in, const int* in_sizes, int n_in,
                              void* d_out, int out_size)
{
    const float* x_feat = (const float*)d_in[0];
    const float* mh_W1  = (const float*)d_in[1];
    const float* mh_b1  = (const float*)d_in[2];
    const float* mh_W2  = (const float*)d_in[3];
    const float* mh_b2  = (const float*)d_in[4];
    const float* mh_W3  = (const float*)d_in[5];
    const float* mh_b3  = (const float*)d_in[6];
    const float* ml_W1  = (const float*)d_in[7];
    const float* ml_b1  = (const float*)d_in[8];
    const float* ml_W2  = (const float*)d_in[9];
    const float* ml_b2  = (const float*)d_in[10];
    const float* ml_W3  = (const float*)d_in[11];
    const float* ml_b3  = (const float*)d_in[12];
    const int*   del_lens = (const int*)d_in[13];
    const int*   mh_len   = (const int*)d_in[14];

    int n = in_sizes[13];
    float* out      = (float*)d_out;
    float* out_bins = out + n;

    dnn_init_kernel<<<1, 64>>>(ml_W1, ml_b1, ml_W2, ml_b2, ml_W3, ml_b3, out_bins);

    int blocks = (n + TPB * EPT - 1) / (TPB * EPT);
    dnn_main_kernel<<<blocks, TPB>>>(x_feat,
                                     mh_W1, mh_b1, mh_W2, mh_b2, mh_W3, mh_b3,
                                     del_lens, mh_len,
                                     out, out_bins, n);
}

// round 7
// speedup vs baseline: 2.2205x; 2.2205x over previous
#include <cuda_runtime.h>

#define NBINS 28
#define HID   16
#define FEAT  8
#define TPB   256

typedef unsigned long long u64;

// mhless table: t[dl] = exp(ml_mlp(dl) - 0.25*dl) for dl = 1..40
__device__ float g_mhless[41];

__device__ __forceinline__ float sigmoid_exact(float v) {
    return 1.0f / (1.0f + __expf(-v));
}

__device__ __forceinline__ u64 pack2(float lo, float hi) {
    u64 r; asm("mov.b64 %0, {%1, %2};" : "=l"(r) : "f"(lo), "f"(hi)); return r;
}
__device__ __forceinline__ void unpack2(u64 v, float& lo, float& hi) {
    asm("mov.b64 {%0, %1}, %2;" : "=f"(lo), "=f"(hi) : "l"(v));
}
__device__ __forceinline__ u64 fma2(u64 a, u64 b, u64 c) {
    u64 d; asm("fma.rn.f32x2 %0, %1, %2, %3;" : "=l"(d) : "l"(a), "l"(b), "l"(c)); return d;
}
__device__ __forceinline__ float tanh_fast(float x) {
    float y; asm("tanh.approx.f32 %0, %1;" : "=f"(y) : "f"(x)); return y;
}

// ---------------------------------------------------------------------------
// Init kernel: exact (expf-sigmoid) ml-MLP table for dl = 1..40; writes
// dl2_scores baseline into out_bins. Runs every launch (d_out is poisoned).
// ---------------------------------------------------------------------------
__global__ void dnn_init_kernel(
    const float* __restrict__ ml_W1, const float* __restrict__ ml_b1,
    const float* __restrict__ ml_W2, const float* __restrict__ ml_b2,
    const float* __restrict__ ml_W3, const float* __restrict__ ml_b3,
    float* __restrict__ out_bins)
{
    int t = threadIdx.x;
    if (t >= 40) return;
    float dl = (float)(t + 1);

    float h1[HID];
    #pragma unroll
    for (int o = 0; o < HID; o++)
        h1[o] = sigmoid_exact(fmaf(dl, ml_W1[o], ml_b1[o]));

    float h2[HID];
    #pragma unroll
    for (int o = 0; o < HID; o++) {
        float a = ml_b2[o];
        #pragma unroll
        for (int i = 0; i < HID; i++)
            a = fmaf(h1[i], ml_W2[i * HID + o], a);
        h2[o] = sigmoid_exact(a);
    }

    float phi = ml_b3[0];
    #pragma unroll
    for (int i = 0; i < HID; i++)
        phi = fmaf(h2[i], ml_W3[i], phi);

    float v = __expf(phi - 0.25f * dl);
    g_mhless[t + 1] = v;
    if (t < NBINS) out_bins[t] = v;
}

// ---------------------------------------------------------------------------
// Main kernel. Tanh-folded MLP (sigmoid(z) = 0.5*tanh(z/2)+0.5):
//   z1' = x·(W1/2) + b1/2                        ; t1 = tanh(z1')  [= 2*sig1-1]
//   z2' = t1·(W2/4) + (b2/2 + colsum(W2)/4)      ; t2 = tanh(z2')  [= 2*sig2-1]
//   phi = t2·(W3/2) + (b3 + sum(W3)/2)
// All matmuls in packed fma.rn.f32x2 over output pairs.
// ---------------------------------------------------------------------------
__global__ __launch_bounds__(TPB, 4)
void dnn_main_kernel(
    const float* __restrict__ x_feat,
    const float* __restrict__ W1, const float* __restrict__ b1,
    const float* __restrict__ W2, const float* __restrict__ b2,
    const float* __restrict__ W3, const float* __restrict__ b3,
    const int*   __restrict__ del_lens,
    const int*   __restrict__ mh_len,
    float* __restrict__ out,
    float* __restrict__ out_bins,
    int n)
{
    __shared__ __align__(16) float sA1[FEAT * HID];   // W1 * 0.5
    __shared__ __align__(16) float sC1[HID];          // b1 * 0.5
    __shared__ __align__(16) float sA2[HID * HID];    // W2 * 0.25
    __shared__ __align__(16) float sC2[HID];          // b2*0.5 + colsum(W2)*0.25
    __shared__ __align__(16) float sA3[HID];          // W3 * 0.5
    __shared__ float sC3;                             // b3 + sum(W3)*0.5
    __shared__ float stab[41];
    __shared__ float sbins[NBINS];

    const int tid = threadIdx.x;

    // ---- staging (all branches reachable with TPB=256) ----
    for (int i = tid; i < FEAT * HID; i += TPB) sA1[i] = 0.5f * W1[i];
    for (int i = tid; i < HID * HID; i += TPB) sA2[i] = 0.25f * W2[i];
    if (tid < HID) {
        sC1[tid] = 0.5f * b1[tid];
        float s = 0.0f;
        #pragma unroll
        for (int i = 0; i < HID; i++) s += W2[i * HID + tid];
        sC2[tid] = fmaf(0.25f, s, 0.5f * b2[tid]);
        sA3[tid] = 0.5f * W3[tid];
    }
    if (tid == 32) {
        float s = 0.0f;
        #pragma unroll
        for (int i = 0; i < HID; i++) s += W3[i];
        sC3 = fmaf(0.5f, s, b3[0]);
    }
    if (tid >= 64 && tid < 64 + 41) stab[tid - 64] = g_mhless[tid - 64];
    if (tid >= 128 && tid < 128 + NBINS) sbins[tid - 128] = 0.0f;
    __syncthreads();

    const int gi = blockIdx.x * TPB + tid;

    if (gi < n) {
        // ---- load features (two float4) ----
        float4 a = *reinterpret_cast<const float4*>(x_feat + (size_t)gi * FEAT);
        float4 c = *reinterpret_cast<const float4*>(x_feat + (size_t)gi * FEAT + 4);
        float x[FEAT] = {a.x, a.y, a.z, a.w, c.x, c.y, c.z, c.w};

        // ---- layer 1: z1' = x @ A1 + C1 (8 output-pairs) ----
        u64 z1[8];
        {
            const ulonglong2* cp = reinterpret_cast<const ulonglong2*>(sC1);
            ulonglong2 c0 = cp[0], c1v = cp[1], c2v = cp[2], c3v = cp[3];
            z1[0] = c0.x;  z1[1] = c0.y;  z1[2] = c1v.x; z1[3] = c1v.y;
            z1[4] = c2v.x; z1[5] = c2v.y; z1[6] = c3v.x; z1[7] = c3v.y;
        }
        #pragma unroll
        for (int i = 0; i < FEAT; i++) {
            u64 xb = pack2(x[i], x[i]);
            const ulonglong2* w = reinterpret_cast<const ulonglong2*>(sA1 + i * HID);
            ulonglong2 wa = w[0], wb = w[1], wc = w[2], wd = w[3];
            z1[0] = fma2(xb, wa.x, z1[0]); z1[1] = fma2(xb, wa.y, z1[1]);
            z1[2] = fma2(xb, wb.x, z1[2]); z1[3] = fma2(xb, wb.y, z1[3]);
            z1[4] = fma2(xb, wc.x, z1[4]); z1[5] = fma2(xb, wc.y, z1[5]);
            z1[6] = fma2(xb, wd.x, z1[6]); z1[7] = fma2(xb, wd.y, z1[7]);
        }

        // ---- tanh (one MUFU per unit) ----
        float t1[HID];
        #pragma unroll
        for (int o = 0; o < 8; o++) {
            float lo, hi; unpack2(z1[o], lo, hi);
            t1[2 * o] = tanh_fast(lo); t1[2 * o + 1] = tanh_fast(hi);
        }

        // ---- layer 2: z2' = t1 @ A2 + C2 ----
        u64 z2[8];
        {
            const ulonglong2* cp = reinterpret_cast<const ulonglong2*>(sC2);
            ulonglong2 c0 = cp[0], c1v = cp[1], c2v = cp[2], c3v = cp[3];
            z2[0] = c0.x;  z2[1] = c0.y;  z2[2] = c1v.x; z2[3] = c1v.y;
            z2[4] = c2v.x; z2[5] = c2v.y; z2[6] = c3v.x; z2[7] = c3v.y;
        }
        #pragma unroll
        for (int i = 0; i < HID; i++) {
            u64 xb = pack2(t1[i], t1[i]);
            const ulonglong2* w = reinterpret_cast<const ulonglong2*>(sA2 + i * HID);
            ulonglong2 wa = w[0], wb = w[1], wc = w[2], wd = w[3];
            z2[0] = fma2(xb, wa.x, z2[0]); z2[1] = fma2(xb, wa.y, z2[1]);
            z2[2] = fma2(xb, wb.x, z2[2]); z2[3] = fma2(xb, wb.y, z2[3]);
            z2[4] = fma2(xb, wc.x, z2[4]); z2[5] = fma2(xb, wc.y, z2[5]);
            z2[6] = fma2(xb, wd.x, z2[6]); z2[7] = fma2(xb, wd.y, z2[7]);
        }

        // ---- tanh + layer 3 ----
        float phi = sC3;
        #pragma unroll
        for (int o = 0; o < 8; o++) {
            float lo, hi; unpack2(z2[o], lo, hi);
            phi = fmaf(tanh_fast(lo), sA3[2 * o],     phi);
            phi = fmaf(tanh_fast(hi), sA3[2 * o + 1], phi);
        }

        // ---- epilogue ----
        int d  = del_lens[gi];
        int mh = mh_len[gi];
        float score = __expf(fmaf(-0.25f, (float)d, phi));
        float contrib = 0.0f;
        if (d == mh && d >= 1 && d <= 40) contrib = stab[d];
        out[gi] = score + contrib;
        if (d <= NBINS) atomicAdd(&sbins[d - 1], score);
    }

    __syncthreads();
    if (tid < NBINS) {
        float v = sbins[tid];
        if (v != 0.0f) atomicAdd(&out_bins[tid], v);
    }
}

// ---------------------------------------------------------------------------
// Launch
// ---------------------------------------------------------------------------
extern "C" void kernel_launch(void* const* d_in, const int* in_sizes, int n_in,
                              void* d_out, int out_size)
{
    const float* x_feat = (const float*)d_in[0];
    const float* mh_W1  = (const float*)d_in[1];
    const float* mh_b1  = (const float*)d_in[2];
    const float* mh_W2  = (const float*)d_in[3];
    const float* mh_b2  = (const float*)d_in[4];
    const float* mh_W3  = (const float*)d_in[5];
    const float* mh_b3  = (const float*)d_in[6];
    const float* ml_W1  = (const float*)d_in[7];
    const float* ml_b1  = (const float*)d_in[8];
    const float* ml_W2  = (const float*)d_in[9];
    const float* ml_b2  = (const float*)d_in[10];
    const float* ml_W3  = (const float*)d_in[11];
    const float* ml_b3  = (const float*)d_in[12];
    const int*   del_lens = (const int*)d_in[13];
    const int*   mh_len   = (const int*)d_in[14];

    int n = in_sizes[13];
    float* out      = (float*)d_out;
    float* out_bins = out + n;

    dnn_init_kernel<<<1, 64>>>(ml_W1, ml_b1, ml_W2, ml_b2, ml_W3, ml_b3, out_bins);

    int blocks = (n + TPB - 1) / TPB;
    dnn_main_kernel<<<blocks, TPB>>>(x_feat,
                                     mh_W1, mh_b1, mh_W2, mh_b2, mh_W3, mh_b3,
                                     del_lens, mh_len,
                                     out, out_bins, n);
}

// round 8
// speedup vs baseline: 2.7332x; 1.2309x over previous
#include <cuda_runtime.h>

#define NBINS 28
#define HID   16
#define FEAT  8
#define TPB   128   // threads per block
#define EPT   2     // elements per thread (weight-load amortization)

typedef unsigned long long u64;

// mhless table: t[dl] = exp(ml_mlp(dl) - 0.25*dl) for dl = 1..40
__device__ float g_mhless[41];

__device__ __forceinline__ float sigmoid_exact(float v) {
    return 1.0f / (1.0f + __expf(-v));
}

__device__ __forceinline__ u64 pack2(float lo, float hi) {
    u64 r; asm("mov.b64 %0, {%1, %2};" : "=l"(r) : "f"(lo), "f"(hi)); return r;
}
__device__ __forceinline__ void unpack2(u64 v, float& lo, float& hi) {
    asm("mov.b64 {%0, %1}, %2;" : "=f"(lo), "=f"(hi) : "l"(v));
}
__device__ __forceinline__ u64 fma2(u64 a, u64 b, u64 c) {
    u64 d; asm("fma.rn.f32x2 %0, %1, %2, %3;" : "=l"(d) : "l"(a), "l"(b), "l"(c)); return d;
}
__device__ __forceinline__ float tanh_fast(float x) {
    float y; asm("tanh.approx.f32 %0, %1;" : "=f"(y) : "f"(x)); return y;
}

// ---------------------------------------------------------------------------
// Init kernel: exact (expf-sigmoid) ml-MLP table for dl = 1..40; writes
// dl2_scores baseline into out_bins. Runs every launch (d_out is poisoned).
// ---------------------------------------------------------------------------
__global__ void dnn_init_kernel(
    const float* __restrict__ ml_W1, const float* __restrict__ ml_b1,
    const float* __restrict__ ml_W2, const float* __restrict__ ml_b2,
    const float* __restrict__ ml_W3, const float* __restrict__ ml_b3,
    float* __restrict__ out_bins)
{
    int t = threadIdx.x;
    if (t >= 40) return;
    float dl = (float)(t + 1);

    float h1[HID];
    #pragma unroll
    for (int o = 0; o < HID; o++)
        h1[o] = sigmoid_exact(fmaf(dl, ml_W1[o], ml_b1[o]));

    float h2[HID];
    #pragma unroll
    for (int o = 0; o < HID; o++) {
        float a = ml_b2[o];
        #pragma unroll
        for (int i = 0; i < HID; i++)
            a = fmaf(h1[i], ml_W2[i * HID + o], a);
        h2[o] = sigmoid_exact(a);
    }

    float phi = ml_b3[0];
    #pragma unroll
    for (int i = 0; i < HID; i++)
        phi = fmaf(h2[i], ml_W3[i], phi);

    float v = __expf(phi - 0.25f * dl);
    g_mhless[t + 1] = v;
    if (t < NBINS) out_bins[t] = v;
}

// ---------------------------------------------------------------------------
// Main kernel. Tanh-folded MLP (sigmoid(z) = 0.5*tanh(z/2)+0.5):
//   z1' = x·(W1/2) + b1/2                        ; t1 = tanh(z1')
//   z2' = t1·(W2/4) + (b2/2 + colsum(W2)/4)      ; t2 = tanh(z2')
//   phi = t2·(W3/2) + (b3 + sum(W3)/2)
// Packed fma.rn.f32x2 over output pairs; EPT=2 shares every weight LDS
// between two elements.
// ---------------------------------------------------------------------------
__global__ __launch_bounds__(TPB, 5)
void dnn_main_kernel(
    const float* __restrict__ x_feat,
    const float* __restrict__ W1, const float* __restrict__ b1,
    const float* __restrict__ W2, const float* __restrict__ b2,
    const float* __restrict__ W3, const float* __restrict__ b3,
    const int*   __restrict__ del_lens,
    const int*   __restrict__ mh_len,
    float* __restrict__ out,
    float* __restrict__ out_bins,
    int n)
{
    __shared__ __align__(16) float sA1[FEAT * HID];   // W1 * 0.5
    __shared__ __align__(16) float sC1[HID];          // b1 * 0.5
    __shared__ __align__(16) float sA2[HID * HID];    // W2 * 0.25
    __shared__ __align__(16) float sC2[HID];          // b2*0.5 + colsum(W2)*0.25
    __shared__ __align__(16) float sA3[HID];          // W3 * 0.5
    __shared__ float sC3;                             // b3 + sum(W3)*0.5
    __shared__ float stab[41];
    __shared__ float sbins[NBINS];

    const int tid = threadIdx.x;

    // ---- staging (TPB = 128) ----
    for (int i = tid; i < FEAT * HID; i += TPB) sA1[i] = 0.5f * W1[i];
    for (int i = tid; i < HID * HID; i += TPB) sA2[i] = 0.25f * W2[i];
    if (tid < HID) {
        sC1[tid] = 0.5f * b1[tid];
        float s = 0.0f;
        #pragma unroll
        for (int i = 0; i < HID; i++) s += W2[i * HID + tid];
        sC2[tid] = fmaf(0.25f, s, 0.5f * b2[tid]);
        sA3[tid] = 0.5f * W3[tid];
    }
    if (tid == 32) {
        float s = 0.0f;
        #pragma unroll
        for (int i = 0; i < HID; i++) s += W3[i];
        sC3 = fmaf(0.5f, s, b3[0]);
    }
    if (tid >= 64 && tid < 64 + 41) stab[tid - 64] = g_mhless[tid - 64];
    if (tid >= 96 && tid < 96 + NBINS) sbins[tid - 96] = 0.0f;
    __syncthreads();

    const int gi0 = blockIdx.x * (TPB * EPT) + tid;
    const int gi1 = gi0 + TPB;
    const bool v0 = (gi0 < n);
    const bool v1 = (gi1 < n);

    // ---- load features for both elements ----
    float x0[FEAT], x1[FEAT];
    {
        int j0 = v0 ? gi0 : 0;
        int j1 = v1 ? gi1 : 0;
        float4 a = *reinterpret_cast<const float4*>(x_feat + (size_t)j0 * FEAT);
        float4 c = *reinterpret_cast<const float4*>(x_feat + (size_t)j0 * FEAT + 4);
        x0[0]=a.x; x0[1]=a.y; x0[2]=a.z; x0[3]=a.w; x0[4]=c.x; x0[5]=c.y; x0[6]=c.z; x0[7]=c.w;
        float4 e = *reinterpret_cast<const float4*>(x_feat + (size_t)j1 * FEAT);
        float4 f = *reinterpret_cast<const float4*>(x_feat + (size_t)j1 * FEAT + 4);
        x1[0]=e.x; x1[1]=e.y; x1[2]=e.z; x1[3]=e.w; x1[4]=f.x; x1[5]=f.y; x1[6]=f.z; x1[7]=f.w;
    }

    // ---- layer 1 ----
    u64 z1a[8], z1b[8];
    {
        const ulonglong2* cp = reinterpret_cast<const ulonglong2*>(sC1);
        ulonglong2 c0 = cp[0], c1v = cp[1], c2v = cp[2], c3v = cp[3];
        z1a[0]=c0.x;  z1a[1]=c0.y;  z1a[2]=c1v.x; z1a[3]=c1v.y;
        z1a[4]=c2v.x; z1a[5]=c2v.y; z1a[6]=c3v.x; z1a[7]=c3v.y;
        #pragma unroll
        for (int o = 0; o < 8; o++) z1b[o] = z1a[o];
    }
    #pragma unroll
    for (int i = 0; i < FEAT; i++) {
        const ulonglong2* w = reinterpret_cast<const ulonglong2*>(sA1 + i * HID);
        ulonglong2 wa = w[0], wb = w[1], wc = w[2], wd = w[3];
        u64 p0 = pack2(x0[i], x0[i]);
        u64 p1 = pack2(x1[i], x1[i]);
        z1a[0]=fma2(p0,wa.x,z1a[0]); z1a[1]=fma2(p0,wa.y,z1a[1]);
        z1a[2]=fma2(p0,wb.x,z1a[2]); z1a[3]=fma2(p0,wb.y,z1a[3]);
        z1a[4]=fma2(p0,wc.x,z1a[4]); z1a[5]=fma2(p0,wc.y,z1a[5]);
        z1a[6]=fma2(p0,wd.x,z1a[6]); z1a[7]=fma2(p0,wd.y,z1a[7]);
        z1b[0]=fma2(p1,wa.x,z1b[0]); z1b[1]=fma2(p1,wa.y,z1b[1]);
        z1b[2]=fma2(p1,wb.x,z1b[2]); z1b[3]=fma2(p1,wb.y,z1b[3]);
        z1b[4]=fma2(p1,wc.x,z1b[4]); z1b[5]=fma2(p1,wc.y,z1b[5]);
        z1b[6]=fma2(p1,wd.x,z1b[6]); z1b[7]=fma2(p1,wd.y,z1b[7]);
    }

    // ---- tanh ----
    float t1a[HID], t1b[HID];
    #pragma unroll
    for (int o = 0; o < 8; o++) {
        float lo, hi;
        unpack2(z1a[o], lo, hi);
        t1a[2*o] = tanh_fast(lo); t1a[2*o+1] = tanh_fast(hi);
        unpack2(z1b[o], lo, hi);
        t1b[2*o] = tanh_fast(lo); t1b[2*o+1] = tanh_fast(hi);
    }

    // ---- layer 2 ----
    u64 z2a[8], z2b[8];
    {
        const ulonglong2* cp = reinterpret_cast<const ulonglong2*>(sC2);
        ulonglong2 c0 = cp[0], c1v = cp[1], c2v = cp[2], c3v = cp[3];
        z2a[0]=c0.x;  z2a[1]=c0.y;  z2a[2]=c1v.x; z2a[3]=c1v.y;
        z2a[4]=c2v.x; z2a[5]=c2v.y; z2a[6]=c3v.x; z2a[7]=c3v.y;
        #pragma unroll
        for (int o = 0; o < 8; o++) z2b[o] = z2a[o];
    }
    #pragma unroll
    for (int i = 0; i < HID; i++) {
        const ulonglong2* w = reinterpret_cast<const ulonglong2*>(sA2 + i * HID);
        ulonglong2 wa = w[0], wb = w[1], wc = w[2], wd = w[3];
        u64 p0 = pack2(t1a[i], t1a[i]);
        u64 p1 = pack2(t1b[i], t1b[i]);
        z2a[0]=fma2(p0,wa.x,z2a[0]); z2a[1]=fma2(p0,wa.y,z2a[1]);
        z2a[2]=fma2(p0,wb.x,z2a[2]); z2a[3]=fma2(p0,wb.y,z2a[3]);
        z2a[4]=fma2(p0,wc.x,z2a[4]); z2a[5]=fma2(p0,wc.y,z2a[5]);
        z2a[6]=fma2(p0,wd.x,z2a[6]); z2a[7]=fma2(p0,wd.y,z2a[7]);
        z2b[0]=fma2(p1,wa.x,z2b[0]); z2b[1]=fma2(p1,wa.y,z2b[1]);
        z2b[2]=fma2(p1,wb.x,z2b[2]); z2b[3]=fma2(p1,wb.y,z2b[3]);
        z2b[4]=fma2(p1,wc.x,z2b[4]); z2b[5]=fma2(p1,wc.y,z2b[5]);
        z2b[6]=fma2(p1,wd.x,z2b[6]); z2b[7]=fma2(p1,wd.y,z2b[7]);
    }

    // ---- tanh + layer 3 ----
    float phi0 = sC3, phi1 = sC3;
    #pragma unroll
    for (int o = 0; o < 8; o++) {
        float w0 = sA3[2*o], w1 = sA3[2*o+1];
        float lo, hi;
        unpack2(z2a[o], lo, hi);
        phi0 = fmaf(tanh_fast(lo), w0, phi0);
        phi0 = fmaf(tanh_fast(hi), w1, phi0);
        unpack2(z2b[o], lo, hi);
        phi1 = fmaf(tanh_fast(lo), w0, phi1);
        phi1 = fmaf(tanh_fast(hi), w1, phi1);
    }

    // ---- epilogue ----
    if (v0) {
        int d  = del_lens[gi0];
        int mh = mh_len[gi0];
        float score = __expf(fmaf(-0.25f, (float)d, phi0));
        float contrib = 0.0f;
        if (d == mh && d >= 1 && d <= 40) contrib = stab[d];
        out[gi0] = score + contrib;
        if (d <= NBINS) atomicAdd(&sbins[d - 1], score);
    }
    if (v1) {
        int d  = del_lens[gi1];
        int mh = mh_len[gi1];
        float score = __expf(fmaf(-0.25f, (float)d, phi1));
        float contrib = 0.0f;
        if (d == mh && d >= 1 && d <= 40) contrib = stab[d];
        out[gi1] = score + contrib;
        if (d <= NBINS) atomicAdd(&sbins[d - 1], score);
    }

    __syncthreads();
    if (tid < NBINS) {
        float v = sbins[tid];
        if (v != 0.0f) atomicAdd(&out_bins[tid], v);
    }
}

// ---------------------------------------------------------------------------
// Launch
// ---------------------------------------------------------------------------
extern "C" void kernel_launch(void* const* d_in, const int* in_sizes, int n_in,
                              void* d_out, int out_size)
{
    const float* x_feat = (const float*)d_in[0];
    const float* mh_W1  = (const float*)d_in[1];
    const float* mh_b1  = (const float*)d_in[2];
    const float* mh_W2  = (const float*)d_in[3];
    const float* mh_b2  = (const float*)d_in[4];
    const float* mh_W3  = (const float*)d_in[5];
    const float* mh_b3  = (const float*)d_in[6];
    const float* ml_W1  = (const float*)d_in[7];
    const float* ml_b1  = (const float*)d_in[8];
    const float* ml_W2  = (const float*)d_in[9];
    const float* ml_b2  = (const float*)d_in[10];
    const float* ml_W3  = (const float*)d_in[11];
    const float* ml_b3  = (const float*)d_in[12];
    const int*   del_lens = (const int*)d_in[13];
    const int*   mh_len   = (const int*)d_in[14];

    int n = in_sizes[13];
    float* out      = (float*)d_out;
    float* out_bins = out + n;

    dnn_init_kernel<<<1, 64>>>(ml_W1, ml_b1, ml_W2, ml_b2, ml_W3, ml_b3, out_bins);

    int blocks = (n + TPB * EPT - 1) / (TPB * EPT);
    dnn_main_kernel<<<blocks, TPB>>>(x_feat,
                                     mh_W1, mh_b1, mh_W2, mh_b2, mh_W3, mh_b3,
                                     del_lens, mh_len,
                                     out, out_bins, n);
}

// round 9
// speedup vs baseline: 2.7798x; 1.0171x over previous
#include <cuda_runtime.h>

#define NBINS 28
#define HID   16
#define FEAT  8
#define TPB   128   // threads per block
#define EPT   3     // elements per thread (weight-load amortization)

typedef unsigned long long u64;

// mhless table: t[dl] = exp(ml_mlp(dl) - 0.25*dl) for dl = 1..40
__device__ float g_mhless[41];

__device__ __forceinline__ float sigmoid_exact(float v) {
    return 1.0f / (1.0f + __expf(-v));
}

__device__ __forceinline__ u64 pack2(float lo, float hi) {
    u64 r; asm("mov.b64 %0, {%1, %2};" : "=l"(r) : "f"(lo), "f"(hi)); return r;
}
__device__ __forceinline__ void unpack2(u64 v, float& lo, float& hi) {
    asm("mov.b64 {%0, %1}, %2;" : "=f"(lo), "=f"(hi) : "l"(v));
}
__device__ __forceinline__ u64 fma2(u64 a, u64 b, u64 c) {
    u64 d; asm("fma.rn.f32x2 %0, %1, %2, %3;" : "=l"(d) : "l"(a), "l"(b), "l"(c)); return d;
}
__device__ __forceinline__ float tanh_fast(float x) {
    float y; asm("tanh.approx.f32 %0, %1;" : "=f"(y) : "f"(x)); return y;
}

// ---------------------------------------------------------------------------
// Init kernel: exact (expf-sigmoid) ml-MLP table for dl = 1..40; writes
// dl2_scores baseline into out_bins. Runs every launch (d_out is poisoned).
// ---------------------------------------------------------------------------
__global__ void dnn_init_kernel(
    const float* __restrict__ ml_W1, const float* __restrict__ ml_b1,
    const float* __restrict__ ml_W2, const float* __restrict__ ml_b2,
    const float* __restrict__ ml_W3, const float* __restrict__ ml_b3,
    float* __restrict__ out_bins)
{
    int t = threadIdx.x;
    if (t >= 40) return;
    float dl = (float)(t + 1);

    float h1[HID];
    #pragma unroll
    for (int o = 0; o < HID; o++)
        h1[o] = sigmoid_exact(fmaf(dl, ml_W1[o], ml_b1[o]));

    float h2[HID];
    #pragma unroll
    for (int o = 0; o < HID; o++) {
        float a = ml_b2[o];
        #pragma unroll
        for (int i = 0; i < HID; i++)
            a = fmaf(h1[i], ml_W2[i * HID + o], a);
        h2[o] = sigmoid_exact(a);
    }

    float phi = ml_b3[0];
    #pragma unroll
    for (int i = 0; i < HID; i++)
        phi = fmaf(h2[i], ml_W3[i], phi);

    float v = __expf(phi - 0.25f * dl);
    g_mhless[t + 1] = v;
    if (t < NBINS) out_bins[t] = v;
}

// ---------------------------------------------------------------------------
// Main kernel. Tanh-folded MLP (sigmoid(z) = 0.5*tanh(z/2)+0.5):
//   z1' = x·(W1/2) + b1/2                        ; t1 = tanh(z1')
//   z2' = t1·(W2/4) + (b2/2 + colsum(W2)/4)      ; t2 = tanh(z2')
//   phi = t2·(W3/2) + (b3 + sum(W3)/2)
// Packed fma.rn.f32x2 over output pairs; EPT=3 shares every weight LDS
// across three elements.
// ---------------------------------------------------------------------------
__global__ __launch_bounds__(TPB, 4)
void dnn_main_kernel(
    const float* __restrict__ x_feat,
    const float* __restrict__ W1, const float* __restrict__ b1,
    const float* __restrict__ W2, const float* __restrict__ b2,
    const float* __restrict__ W3, const float* __restrict__ b3,
    const int*   __restrict__ del_lens,
    const int*   __restrict__ mh_len,
    float* __restrict__ out,
    float* __restrict__ out_bins,
    int n)
{
    __shared__ __align__(16) float sA1[FEAT * HID];   // W1 * 0.5
    __shared__ __align__(16) float sC1[HID];          // b1 * 0.5
    __shared__ __align__(16) float sA2[HID * HID];    // W2 * 0.25
    __shared__ __align__(16) float sC2[HID];          // b2*0.5 + colsum(W2)*0.25
    __shared__ __align__(16) float sA3[HID];          // W3 * 0.5
    __shared__ float sC3;                             // b3 + sum(W3)*0.5
    __shared__ float stab[41];
    __shared__ float sbins[NBINS];

    const int tid = threadIdx.x;

    // ---- staging (TPB = 128) ----
    for (int i = tid; i < FEAT * HID; i += TPB) sA1[i] = 0.5f * W1[i];
    for (int i = tid; i < HID * HID; i += TPB) sA2[i] = 0.25f * W2[i];
    if (tid < HID) {
        sC1[tid] = 0.5f * b1[tid];
        float s = 0.0f;
        #pragma unroll
        for (int i = 0; i < HID; i++) s += W2[i * HID + tid];
        sC2[tid] = fmaf(0.25f, s, 0.5f * b2[tid]);
        sA3[tid] = 0.5f * W3[tid];
    }
    if (tid == 32) {
        float s = 0.0f;
        #pragma unroll
        for (int i = 0; i < HID; i++) s += W3[i];
        sC3 = fmaf(0.5f, s, b3[0]);
    }
    if (tid >= 64 && tid < 64 + 41) stab[tid - 64] = g_mhless[tid - 64];
    if (tid >= 96 && tid < 96 + NBINS) sbins[tid - 96] = 0.0f;
    __syncthreads();

    int  gi[EPT];
    bool vv[EPT];
    #pragma unroll
    for (int e = 0; e < EPT; e++) {
        gi[e] = blockIdx.x * (TPB * EPT) + e * TPB + tid;
        vv[e] = (gi[e] < n);
    }

    // ---- load features ----
    float x[EPT][FEAT];
    #pragma unroll
    for (int e = 0; e < EPT; e++) {
        int j = vv[e] ? gi[e] : 0;
        float4 a = *reinterpret_cast<const float4*>(x_feat + (size_t)j * FEAT);
        float4 c = *reinterpret_cast<const float4*>(x_feat + (size_t)j * FEAT + 4);
        x[e][0]=a.x; x[e][1]=a.y; x[e][2]=a.z; x[e][3]=a.w;
        x[e][4]=c.x; x[e][5]=c.y; x[e][6]=c.z; x[e][7]=c.w;
    }

    // ---- layer 1 ----
    u64 z1[EPT][8];
    {
        const ulonglong2* cp = reinterpret_cast<const ulonglong2*>(sC1);
        ulonglong2 c0 = cp[0], c1v = cp[1], c2v = cp[2], c3v = cp[3];
        #pragma unroll
        for (int e = 0; e < EPT; e++) {
            z1[e][0]=c0.x;  z1[e][1]=c0.y;  z1[e][2]=c1v.x; z1[e][3]=c1v.y;
            z1[e][4]=c2v.x; z1[e][5]=c2v.y; z1[e][6]=c3v.x; z1[e][7]=c3v.y;
        }
    }
    #pragma unroll
    for (int i = 0; i < FEAT; i++) {
        const ulonglong2* w = reinterpret_cast<const ulonglong2*>(sA1 + i * HID);
        ulonglong2 wa = w[0], wb = w[1], wc = w[2], wd = w[3];
        #pragma unroll
        for (int e = 0; e < EPT; e++) {
            u64 p = pack2(x[e][i], x[e][i]);
            z1[e][0]=fma2(p,wa.x,z1[e][0]); z1[e][1]=fma2(p,wa.y,z1[e][1]);
            z1[e][2]=fma2(p,wb.x,z1[e][2]); z1[e][3]=fma2(p,wb.y,z1[e][3]);
            z1[e][4]=fma2(p,wc.x,z1[e][4]); z1[e][5]=fma2(p,wc.y,z1[e][5]);
            z1[e][6]=fma2(p,wd.x,z1[e][6]); z1[e][7]=fma2(p,wd.y,z1[e][7]);
        }
    }

    // ---- tanh ----
    float t1[EPT][HID];
    #pragma unroll
    for (int e = 0; e < EPT; e++)
        #pragma unroll
        for (int o = 0; o < 8; o++) {
            float lo, hi; unpack2(z1[e][o], lo, hi);
            t1[e][2*o] = tanh_fast(lo); t1[e][2*o+1] = tanh_fast(hi);
        }

    // ---- layer 2 ----
    u64 z2[EPT][8];
    {
        const ulonglong2* cp = reinterpret_cast<const ulonglong2*>(sC2);
        ulonglong2 c0 = cp[0], c1v = cp[1], c2v = cp[2], c3v = cp[3];
        #pragma unroll
        for (int e = 0; e < EPT; e++) {
            z2[e][0]=c0.x;  z2[e][1]=c0.y;  z2[e][2]=c1v.x; z2[e][3]=c1v.y;
            z2[e][4]=c2v.x; z2[e][5]=c2v.y; z2[e][6]=c3v.x; z2[e][7]=c3v.y;
        }
    }
    #pragma unroll
    for (int i = 0; i < HID; i++) {
        const ulonglong2* w = reinterpret_cast<const ulonglong2*>(sA2 + i * HID);
        ulonglong2 wa = w[0], wb = w[1], wc = w[2], wd = w[3];
        #pragma unroll
        for (int e = 0; e < EPT; e++) {
            u64 p = pack2(t1[e][i], t1[e][i]);
            z2[e][0]=fma2(p,wa.x,z2[e][0]); z2[e][1]=fma2(p,wa.y,z2[e][1]);
            z2[e][2]=fma2(p,wb.x,z2[e][2]); z2[e][3]=fma2(p,wb.y,z2[e][3]);
            z2[e][4]=fma2(p,wc.x,z2[e][4]); z2[e][5]=fma2(p,wc.y,z2[e][5]);
            z2[e][6]=fma2(p,wd.x,z2[e][6]); z2[e][7]=fma2(p,wd.y,z2[e][7]);
        }
    }

    // ---- tanh + layer 3 ----
    float phi[EPT];
    #pragma unroll
    for (int e = 0; e < EPT; e++) phi[e] = sC3;
    #pragma unroll
    for (int o = 0; o < 8; o++) {
        float w0 = sA3[2*o], w1 = sA3[2*o+1];
        #pragma unroll
        for (int e = 0; e < EPT; e++) {
            float lo, hi; unpack2(z2[e][o], lo, hi);
            phi[e] = fmaf(tanh_fast(lo), w0, phi[e]);
            phi[e] = fmaf(tanh_fast(hi), w1, phi[e]);
        }
    }

    // ---- epilogue ----
    #pragma unroll
    for (int e = 0; e < EPT; e++) {
        if (vv[e]) {
            int d  = del_lens[gi[e]];
            int mh = mh_len[gi[e]];
            float score = __expf(fmaf(-0.25f, (float)d, phi[e]));
            float contrib = 0.0f;
            if (d == mh && d >= 1 && d <= 40) contrib = stab[d];
            out[gi[e]] = score + contrib;
            if (d <= NBINS) atomicAdd(&sbins[d - 1], score);
        }
    }

    __syncthreads();
    if (tid < NBINS) {
        float v = sbins[tid];
        if (v != 0.0f) atomicAdd(&out_bins[tid], v);
    }
}

// ---------------------------------------------------------------------------
// Launch
// ---------------------------------------------------------------------------
extern "C" void kernel_launch(void* const* d_in, const int* in_sizes, int n_in,
                              void* d_out, int out_size)
{
    const float* x_feat = (const float*)d_in[0];
    const float* mh_W1  = (const float*)d_in[1];
    const float* mh_b1  = (const float*)d_in[2];
    const float* mh_W2  = (const float*)d_in[3];
    const float* mh_b2  = (const float*)d_in[4];
    const float* mh_W3  = (const float*)d_in[5];
    const float* mh_b3  = (const float*)d_in[6];
    const float* ml_W1  = (const float*)d_in[7];
    const float* ml_b1  = (const float*)d_in[8];
    const float* ml_W2  = (const float*)d_in[9];
    const float* ml_b2  = (const float*)d_in[10];
    const float* ml_W3  = (const float*)d_in[11];
    const float* ml_b3  = (const float*)d_in[12];
    const int*   del_lens = (const int*)d_in[13];
    const int*   mh_len   = (const int*)d_in[14];

    int n = in_sizes[13];
    float* out      = (float*)d_out;
    float* out_bins = out + n;

    dnn_init_kernel<<<1, 64>>>(ml_W1, ml_b1, ml_W2, ml_b2, ml_W3, ml_b3, out_bins);

    int blocks = (n + TPB * EPT - 1) / (TPB * EPT);
    dnn_main_kernel<<<blocks, TPB>>>(x_feat,
                                     mh_W1, mh_b1, mh_W2, mh_b2, mh_W3, mh_b3,
                                     del_lens, mh_len,
                                     out, out_bins, n);
}

// round 10
// speedup vs baseline: 3.4115x; 1.2273x over previous
#include <cuda_runtime.h>

#define NBINS 28
#define HID   16
#define FEAT  8
#define TPB   128   // threads per block
#define EPT   3     // elements per thread (weight-load amortization)

typedef unsigned long long u64;

// mhless table: t[dl] = exp(ml_mlp(dl) - 0.25*dl) for dl = 1..40
__device__ float g_mhless[41];

__device__ __forceinline__ float sigmoid_exact(float v) {
    return 1.0f / (1.0f + __expf(-v));
}

__device__ __forceinline__ u64 pack2(float lo, float hi) {
    u64 r; asm("mov.b64 %0, {%1, %2};" : "=l"(r) : "f"(lo), "f"(hi)); return r;
}
__device__ __forceinline__ void unpack2(u64 v, float& lo, float& hi) {
    asm("mov.b64 {%0, %1}, %2;" : "=f"(lo), "=f"(hi) : "l"(v));
}
__device__ __forceinline__ u64 fma2(u64 a, u64 b, u64 c) {
    u64 d; asm("fma.rn.f32x2 %0, %1, %2, %3;" : "=l"(d) : "l"(a), "l"(b), "l"(c)); return d;
}
__device__ __forceinline__ float tanh_fast(float x) {
    float y; asm("tanh.approx.f32 %0, %1;" : "=f"(y) : "f"(x)); return y;
}

// ---------------------------------------------------------------------------
// Init kernel: exact (expf-sigmoid) ml-MLP table for dl = 1..40; writes
// dl2_scores baseline into out_bins. Runs every launch (d_out is poisoned).
// ---------------------------------------------------------------------------
__global__ void dnn_init_kernel(
    const float* __restrict__ ml_W1, const float* __restrict__ ml_b1,
    const float* __restrict__ ml_W2, const float* __restrict__ ml_b2,
    const float* __restrict__ ml_W3, const float* __restrict__ ml_b3,
    float* __restrict__ out_bins)
{
    int t = threadIdx.x;
    if (t >= 40) return;
    float dl = (float)(t + 1);

    float h1[HID];
    #pragma unroll
    for (int o = 0; o < HID; o++)
        h1[o] = sigmoid_exact(fmaf(dl, ml_W1[o], ml_b1[o]));

    float h2[HID];
    #pragma unroll
    for (int o = 0; o < HID; o++) {
        float a = ml_b2[o];
        #pragma unroll
        for (int i = 0; i < HID; i++)
            a = fmaf(h1[i], ml_W2[i * HID + o], a);
        h2[o] = sigmoid_exact(a);
    }

    float phi = ml_b3[0];
    #pragma unroll
    for (int i = 0; i < HID; i++)
        phi = fmaf(h2[i], ml_W3[i], phi);

    float v = __expf(phi - 0.25f * dl);
    g_mhless[t + 1] = v;
    if (t < NBINS) out_bins[t] = v;
}

// ---------------------------------------------------------------------------
// Main kernel. Tanh-folded MLP (sigmoid(z) = 0.5*tanh(z/2)+0.5):
//   z1' = x·(W1/2) + b1/2                        ; t1 = tanh(z1')
//   z2' = t1·(W2/4) + (b2/2 + colsum(W2)/4)      ; t2 = tanh(z2')
//   phi = t2·(W3/2) + (b3 + sum(W3)/2)
// Packed fma.rn.f32x2; EPT=3 shares each weight LDS across three elements.
// All per-element LDGs issued BEFORE weight staging so DRAM latency hides
// behind the staging chain + barrier.
// ---------------------------------------------------------------------------
__global__ __launch_bounds__(TPB, 4)
void dnn_main_kernel(
    const float* __restrict__ x_feat,
    const float* __restrict__ W1, const float* __restrict__ b1,
    const float* __restrict__ W2, const float* __restrict__ b2,
    const float* __restrict__ W3, const float* __restrict__ b3,
    const int*   __restrict__ del_lens,
    const int*   __restrict__ mh_len,
    float* __restrict__ out,
    float* __restrict__ out_bins,
    int n)
{
    __shared__ __align__(16) float sA1[FEAT * HID];   // W1 * 0.5
    __shared__ __align__(16) float sC1[HID];          // b1 * 0.5
    __shared__ __align__(16) float sA2[HID * HID];    // W2 * 0.25
    __shared__ __align__(16) float sC2[HID];          // b2*0.5 + colsum(W2)*0.25
    __shared__ __align__(16) float sA3[HID];          // W3 * 0.5
    __shared__ float sC3;                             // b3 + sum(W3)*0.5
    __shared__ float stab[41];
    __shared__ float sbins[NBINS];

    const int tid = threadIdx.x;

    // ---- per-element global loads FIRST (latency hidden behind staging) ----
    int  gi[EPT];
    bool vv[EPT];
    #pragma unroll
    for (int e = 0; e < EPT; e++) {
        gi[e] = blockIdx.x * (TPB * EPT) + e * TPB + tid;
        vv[e] = (gi[e] < n);
    }

    float x[EPT][FEAT];
    int   dreg[EPT], mreg[EPT];
    #pragma unroll
    for (int e = 0; e < EPT; e++) {
        int j = vv[e] ? gi[e] : 0;
        float4 a = *reinterpret_cast<const float4*>(x_feat + (size_t)j * FEAT);
        float4 c = *reinterpret_cast<const float4*>(x_feat + (size_t)j * FEAT + 4);
        x[e][0]=a.x; x[e][1]=a.y; x[e][2]=a.z; x[e][3]=a.w;
        x[e][4]=c.x; x[e][5]=c.y; x[e][6]=c.z; x[e][7]=c.w;
        dreg[e] = del_lens[j];
        mreg[e] = mh_len[j];
    }

    // ---- staging (TPB = 128) ----
    for (int i = tid; i < FEAT * HID; i += TPB) sA1[i] = 0.5f * W1[i];
    for (int i = tid; i < HID * HID; i += TPB) sA2[i] = 0.25f * W2[i];
    if (tid < HID) {
        sC1[tid] = 0.5f * b1[tid];
        float s = 0.0f;
        #pragma unroll
        for (int i = 0; i < HID; i++) s += W2[i * HID + tid];
        sC2[tid] = fmaf(0.25f, s, 0.5f * b2[tid]);
        sA3[tid] = 0.5f * W3[tid];
    }
    if (tid == 32) {
        float s = 0.0f;
        #pragma unroll
        for (int i = 0; i < HID; i++) s += W3[i];
        sC3 = fmaf(0.5f, s, b3[0]);
    }
    if (tid >= 64 && tid < 64 + 41) stab[tid - 64] = g_mhless[tid - 64];
    if (tid >= 96 && tid < 96 + NBINS) sbins[tid - 96] = 0.0f;
    __syncthreads();

    // ---- layer 1 ----
    u64 z1[EPT][8];
    {
        const ulonglong2* cp = reinterpret_cast<const ulonglong2*>(sC1);
        ulonglong2 c0 = cp[0], c1v = cp[1], c2v = cp[2], c3v = cp[3];
        #pragma unroll
        for (int e = 0; e < EPT; e++) {
            z1[e][0]=c0.x;  z1[e][1]=c0.y;  z1[e][2]=c1v.x; z1[e][3]=c1v.y;
            z1[e][4]=c2v.x; z1[e][5]=c2v.y; z1[e][6]=c3v.x; z1[e][7]=c3v.y;
        }
    }
    #pragma unroll
    for (int i = 0; i < FEAT; i++) {
        const ulonglong2* w = reinterpret_cast<const ulonglong2*>(sA1 + i * HID);
        ulonglong2 wa = w[0], wb = w[1], wc = w[2], wd = w[3];
        #pragma unroll
        for (int e = 0; e < EPT; e++) {
            u64 p = pack2(x[e][i], x[e][i]);
            z1[e][0]=fma2(p,wa.x,z1[e][0]); z1[e][1]=fma2(p,wa.y,z1[e][1]);
            z1[e][2]=fma2(p,wb.x,z1[e][2]); z1[e][3]=fma2(p,wb.y,z1[e][3]);
            z1[e][4]=fma2(p,wc.x,z1[e][4]); z1[e][5]=fma2(p,wc.y,z1[e][5]);
            z1[e][6]=fma2(p,wd.x,z1[e][6]); z1[e][7]=fma2(p,wd.y,z1[e][7]);
        }
    }

    // ---- tanh ----
    float t1[EPT][HID];
    #pragma unroll
    for (int e = 0; e < EPT; e++)
        #pragma unroll
        for (int o = 0; o < 8; o++) {
            float lo, hi; unpack2(z1[e][o], lo, hi);
            t1[e][2*o] = tanh_fast(lo); t1[e][2*o+1] = tanh_fast(hi);
        }

    // ---- layer 2 ----
    u64 z2[EPT][8];
    {
        const ulonglong2* cp = reinterpret_cast<const ulonglong2*>(sC2);
        ulonglong2 c0 = cp[0], c1v = cp[1], c2v = cp[2], c3v = cp[3];
        #pragma unroll
        for (int e = 0; e < EPT; e++) {
            z2[e][0]=c0.x;  z2[e][1]=c0.y;  z2[e][2]=c1v.x; z2[e][3]=c1v.y;
            z2[e][4]=c2v.x; z2[e][5]=c2v.y; z2[e][6]=c3v.x; z2[e][7]=c3v.y;
        }
    }
    #pragma unroll
    for (int i = 0; i < HID; i++) {
        const ulonglong2* w = reinterpret_cast<const ulonglong2*>(sA2 + i * HID);
        ulonglong2 wa = w[0], wb = w[1], wc = w[2], wd = w[3];
        #pragma unroll
        for (int e = 0; e < EPT; e++) {
            u64 p = pack2(t1[e][i], t1[e][i]);
            z2[e][0]=fma2(p,wa.x,z2[e][0]); z2[e][1]=fma2(p,wa.y,z2[e][1]);
            z2[e][2]=fma2(p,wb.x,z2[e][2]); z2[e][3]=fma2(p,wb.y,z2[e][3]);
            z2[e][4]=fma2(p,wc.x,z2[e][4]); z2[e][5]=fma2(p,wc.y,z2[e][5]);
            z2[e][6]=fma2(p,wd.x,z2[e][6]); z2[e][7]=fma2(p,wd.y,z2[e][7]);
        }
    }

    // ---- tanh + layer 3 ----
    float phi[EPT];
    #pragma unroll
    for (int e = 0; e < EPT; e++) phi[e] = sC3;
    #pragma unroll
    for (int o = 0; o < 8; o++) {
        float w0 = sA3[2*o], w1 = sA3[2*o+1];
        #pragma unroll
        for (int e = 0; e < EPT; e++) {
            float lo, hi; unpack2(z2[e][o], lo, hi);
            phi[e] = fmaf(tanh_fast(lo), w0, phi[e]);
            phi[e] = fmaf(tanh_fast(hi), w1, phi[e]);
        }
    }

    // ---- epilogue (no memory dependencies left: d/mh already in regs) ----
    #pragma unroll
    for (int e = 0; e < EPT; e++) {
        if (vv[e]) {
            int d  = dreg[e];
            int mh = mreg[e];
            float score = __expf(fmaf(-0.25f, (float)d, phi[e]));
            float contrib = 0.0f;
            if (d == mh && d >= 1 && d <= 40) contrib = stab[d];
            out[gi[e]] = score + contrib;
            if (d <= NBINS) atomicAdd(&sbins[d - 1], score);
        }
    }

    __syncthreads();
    if (tid < NBINS) {
        float v = sbins[tid];
        if (v != 0.0f) atomicAdd(&out_bins[tid], v);
    }
}

// ---------------------------------------------------------------------------
// Launch
// ---------------------------------------------------------------------------
extern "C" void kernel_launch(void* const* d_in, const int* in_sizes, int n_in,
                              void* d_out, int out_size)
{
    const float* x_feat = (const float*)d_in[0];
    const float* mh_W1  = (const float*)d_in[1];
    const float* mh_b1  = (const float*)d_in[2];
    const float* mh_W2  = (const float*)d_in[3];
    const float* mh_b2  = (const float*)d_in[4];
    const float* mh_W3  = (const float*)d_in[5];
    const float* mh_b3  = (const float*)d_in[6];
    const float* ml_W1  = (const float*)d_in[7];
    const float* ml_b1  = (const float*)d_in[8];
    const float* ml_W2  = (const float*)d_in[9];
    const float* ml_b2  = (const float*)d_in[10];
    const float* ml_W3  = (const float*)d_in[11];
    const float* ml_b3  = (const float*)d_in[12];
    const int*   del_lens = (const int*)d_in[13];
    const int*   mh_len   = (const int*)d_in[14];

    int n = in_sizes[13];
    float* out      = (float*)d_out;
    float* out_bins = out + n;

    dnn_init_kernel<<<1, 64>>>(ml_W1, ml_b1, ml_W2, ml_b2, ml_W3, ml_b3, out_bins);

    int blocks = (n + TPB * EPT - 1) / (TPB * EPT);
    dnn_main_kernel<<<blocks, TPB>>>(x_feat,
                                     mh_W1, mh_b1, mh_W2, mh_b2, mh_W3, mh_b3,
                                     del_lens, mh_len,
                                     out, out_bins, n);
}